// round 14
// baseline (speedup 1.0000x reference)
#include <cuda_runtime.h>

typedef unsigned long long u64;

#define N_FFT   1024
#define THREADS 64                        // 2 warps = 2 rows in flight per CTA
#define BLOCKS  1824                      // 152 SMs * 12 resident CTAs = 1 wave
#define ROWPAD(a) ((a) + ((a) >> 5))      // 64-bit padding, conflict-free
#define SMEM_C    (N_FFT + (N_FFT >> 5))  // 1056 packed complex per row

// ── packed complex primitives: p = (re in lo, im in hi) ──────────────────
__device__ __forceinline__ u64 cpack(float r, float i) {
    u64 p; asm("mov.b64 %0,{%1,%2};" : "=l"(p) : "f"(r), "f"(i)); return p;
}
__device__ __forceinline__ void cunpack(u64 p, float& r, float& i) {
    asm("mov.b64 {%0,%1},%2;" : "=f"(r), "=f"(i) : "l"(p));
}
__device__ __forceinline__ u64 cadd(u64 a, u64 b) {
    u64 o; asm("add.rn.f32x2 %0,%1,%2;" : "=l"(o) : "l"(a), "l"(b)); return o;
}
__device__ __forceinline__ u64 cmul2(u64 a, u64 b) {
    u64 o; asm("mul.rn.f32x2 %0,%1,%2;" : "=l"(o) : "l"(a), "l"(b)); return o;
}
__device__ __forceinline__ u64 cfma(u64 a, u64 b, u64 c) {
    u64 o; asm("fma.rn.f32x2 %0,%1,%2,%3;" : "=l"(o) : "l"(a), "l"(b), "l"(c)); return o;
}
// a - b  ==  fma(b, (-1,-1), a)
__device__ __forceinline__ u64 csub(u64 a, u64 b, u64 n1) { return cfma(b, n1, a); }
__device__ __forceinline__ u64 cswap(u64 a) {              // (re,im) -> (im,re)
    float r, i; cunpack(a, r, i); return cpack(i, r);
}
// multiply by +i: (re,im) -> (-im, re)
__device__ __forceinline__ u64 imul(u64 a) { return cswap(a) ^ 0x80000000ULL; }
// a * (c + i s) with t1=(c,c), t2=(-s,s)
__device__ __forceinline__ u64 cmulw(u64 a, u64 t1, u64 t2) {
    return cfma(cswap(a), t2, cmul2(a, t1));
}

// ── W32 twiddle tables: W32^k = cos(pi k/16) + i sin(pi k/16), k=0..21 ──
__constant__ float2 W32T1[22] = {
    { 1.0f, 1.0f},
    { 0.98078528040323044913f,  0.98078528040323044913f},
    { 0.92387953251128675613f,  0.92387953251128675613f},
    { 0.83146961230254523708f,  0.83146961230254523708f},
    { 0.70710678118654752440f,  0.70710678118654752440f},
    { 0.55557023301960222474f,  0.55557023301960222474f},
    { 0.38268343236508977173f,  0.38268343236508977173f},
    { 0.19509032201612826785f,  0.19509032201612826785f},
    { 0.0f, 0.0f},
    {-0.19509032201612826785f, -0.19509032201612826785f},
    {-0.38268343236508977173f, -0.38268343236508977173f},
    {-0.55557023301960222474f, -0.55557023301960222474f},
    {-0.70710678118654752440f, -0.70710678118654752440f},
    {-0.83146961230254523708f, -0.83146961230254523708f},
    {-0.92387953251128675613f, -0.92387953251128675613f},
    {-0.98078528040323044913f, -0.98078528040323044913f},
    {-1.0f, -1.0f},
    {-0.98078528040323044913f, -0.98078528040323044913f},
    {-0.92387953251128675613f, -0.92387953251128675613f},
    {-0.83146961230254523708f, -0.83146961230254523708f},
    {-0.70710678118654752440f, -0.70710678118654752440f},
    {-0.55557023301960222474f, -0.55557023301960222474f} };
__constant__ float2 W32T2[22] = {
    { 0.0f, 0.0f},
    {-0.19509032201612826785f,  0.19509032201612826785f},
    {-0.38268343236508977173f,  0.38268343236508977173f},
    {-0.55557023301960222474f,  0.55557023301960222474f},
    {-0.70710678118654752440f,  0.70710678118654752440f},
    {-0.83146961230254523708f,  0.83146961230254523708f},
    {-0.92387953251128675613f,  0.92387953251128675613f},
    {-0.98078528040323044913f,  0.98078528040323044913f},
    {-1.0f, 1.0f},
    {-0.98078528040323044913f,  0.98078528040323044913f},
    {-0.92387953251128675613f,  0.92387953251128675613f},
    {-0.83146961230254523708f,  0.83146961230254523708f},
    {-0.70710678118654752440f,  0.70710678118654752440f},
    {-0.55557023301960222474f,  0.55557023301960222474f},
    {-0.38268343236508977173f,  0.38268343236508977173f},
    {-0.19509032201612826785f,  0.19509032201612826785f},
    { 0.0f, 0.0f},
    { 0.19509032201612826785f, -0.19509032201612826785f},
    { 0.38268343236508977173f, -0.38268343236508977173f},
    { 0.55557023301960222474f, -0.55557023301960222474f},
    { 0.70710678118654752440f, -0.70710678118654752440f},
    { 0.83146961230254523708f, -0.83146961230254523708f} };

// Inverse radix-4 in packed regs (sign +i).
__device__ __forceinline__ void r4inv(u64& u0, u64& u1, u64& u2, u64& u3, u64 n1) {
    u64 a0 = cadd(u0, u2), a1 = csub(u0, u2, n1);
    u64 a2 = cadd(u1, u3), a3 = csub(u1, u3, n1);
    u0 = cadd(a0, a2);
    u2 = csub(a0, a2, n1);
    u64 d = imul(a3);
    u1 = cadd(a1, d);
    u3 = csub(a1, d, n1);
}

// Inverse DFT-8 in-place on 8 consecutive slots; output y_q at slot q.
__device__ __forceinline__ void dft8inv(u64* b, u64 n1, u64 c7t1, u64 c7t2, u64 c7t1n) {
    r4inv(b[0], b[2], b[4], b[6], n1);   // E_q -> slot 2q
    r4inv(b[1], b[3], b[5], b[7], n1);   // O_q -> slot 2q+1
    b[3] = cmulw(b[3], c7t1,  c7t2);     // O1 *= W8   ( C+iC)
    b[5] = imul(b[5]);                   // O2 *= i
    b[7] = cmulw(b[7], c7t1n, c7t2);     // O3 *= W8^3 (-C+iC)
    const u64 e0 = b[0], e1 = b[2], e2 = b[4], e3 = b[6];
    const u64 o0 = b[1], o1 = b[3], o2 = b[5], o3 = b[7];
    b[0] = cadd(e0, o0);  b[1] = cadd(e1, o1);
    b[2] = cadd(e2, o2);  b[3] = cadd(e3, o3);
    b[4] = csub(e0, o0, n1);  b[5] = csub(e1, o1, n1);
    b[6] = csub(e2, o2, n1);  b[7] = csub(e3, o3, n1);
}

// Inverse DFT-32 in registers. Output: slot 8*(q&3) + (q>>2) holds y_q.
__device__ __forceinline__ void butterfly32(u64* x, u64 n1) {
    #pragma unroll
    for (int m2 = 0; m2 < 8; ++m2)
        r4inv(x[m2], x[m2 + 8], x[m2 + 16], x[m2 + 24], n1);
    #pragma unroll
    for (int q1 = 1; q1 < 4; ++q1)
        #pragma unroll
        for (int m2 = 1; m2 < 8; ++m2) {
            const float2 t1 = W32T1[q1 * m2];
            const float2 t2 = W32T2[q1 * m2];
            x[m2 + 8 * q1] = cmulw(x[m2 + 8 * q1],
                                   cpack(t1.x, t1.y), cpack(t2.x, t2.y));
        }
    const float C = 0.70710678118654752440f;
    const u64 c7t1  = cpack( C,  C);
    const u64 c7t2  = cpack(-C,  C);
    const u64 c7t1n = cpack(-C, -C);
    #pragma unroll
    for (int q1 = 0; q1 < 4; ++q1)
        dft8inv(x + 8 * q1, n1, c7t1, c7t2, c7t1n);
}

__global__ void __launch_bounds__(THREADS) ifft1024_r32ps_kernel(
    const float* __restrict__ re_in,
    const float* __restrict__ im_in,
    float* __restrict__ out,
    long long half_out,
    int n_rows)
{
    __shared__ u64 sbuf[2][SMEM_C];

    const int t   = threadIdx.x & 31;         // lane = position within row
    const int wid = threadIdx.x >> 5;         // warp = row within CTA
    const int warp_gid = blockIdx.x * 2 + wid;
    const int W = gridDim.x * 2;              // total warps (single wave)
    const float TWO_PI = 6.28318530717958647692f;
    const u64 n1 = cpack(-1.0f, -1.0f);

    for (long long row = warp_gid; row < n_rows; row += W) {
        const long long base = row * N_FFT;

        u64 x[32];

        // ── Pass 1 loads: coalesced, streaming (read-once). ──
        #pragma unroll
        for (int m = 0; m < 32; ++m)
            x[m] = cpack(__ldcs(re_in + base + t + 32 * m),
                         __ldcs(im_in + base + t + 32 * m));

        // ── Prefetch next row into L2 while this row computes. ──
        if (row + W < n_rows) {
            const long long nbase = base + (long long)W * N_FFT;
            asm volatile("prefetch.global.L2 [%0];" ::
                         "l"(re_in + nbase + 32 * t));   // lane t: line t (128B)
            asm volatile("prefetch.global.L2 [%0];" ::
                         "l"(im_in + nbase + 32 * t));
        }

        butterfly32(x, n1);

        // Write y_q to position 32t + q (warp-private region, conflict-free)
        #pragma unroll
        for (int q = 0; q < 32; ++q) {
            const int s = ((q & 3) << 3) + (q >> 2);
            sbuf[wid][ROWPAD(32 * t + q)] = x[s];
        }
        __syncwarp();

        // ── Pass 2: radix-32, p=32, k=t. Read legs at position t + 32m. ──
        #pragma unroll
        for (int m = 0; m < 32; ++m)
            x[m] = sbuf[wid][t + 33 * m];     // ROWPAD(t + 32m) = t + 33m
        __syncwarp();                         // reads done before next iter's writes

        // Twiddle u_m *= w^m, w = exp(+2*pi*i*t/1024); chain re-anchored every 8.
        {
            const float ang = TWO_PI * (float)t * (1.0f / 1024.0f);
            float c1, s1;
            __sincosf(ang, &s1, &c1);
            const u64 w1t1 = cpack(c1, c1);
            const u64 w1t2 = cpack(-s1, s1);
            #pragma unroll
            for (int j = 0; j < 4; ++j) {
                float cr, ci;
                if (j == 0) { cr = 1.0f; ci = 0.0f; }
                else        { __sincosf(ang * (float)(8 * j), &ci, &cr); }
                u64 ch = cpack(cr, ci);
                #pragma unroll
                for (int r = 0; r < 8; ++r) {
                    const int m = 8 * j + r;
                    if (m > 0) {
                        float hr, hi;
                        cunpack(ch, hr, hi);
                        x[m] = cmulw(x[m], cpack(hr, hr), cpack(-hi, hi));
                    }
                    ch = cmulw(ch, w1t1, w1t2);
                }
            }
        }
        butterfly32(x, n1);

        // ── Store: y_q at natural position t + 32q; coalesced streaming stores. ──
        const float scale = 1.0f / (float)N_FFT;
        const u64 ks = cpack(scale, scale);
        #pragma unroll
        for (int q = 0; q < 32; ++q) {
            const int s = ((q & 3) << 3) + (q >> 2);
            float vr, vi;
            cunpack(cmul2(x[s], ks), vr, vi);
            __stcs(out + base + t + 32 * q, vr);
            __stcs(out + half_out + base + t + 32 * q, vi);
        }
    }
}

extern "C" void kernel_launch(void* const* d_in, const int* in_sizes, int n_in,
                              void* d_out, int out_size) {
    const float* re = (const float*)d_in[0];
    const float* im = (const float*)d_in[1];
    float* out = (float*)d_out;

    const int n_elems = in_sizes[0];                 // 8*4096*1024
    const int rows = n_elems / N_FFT;                // 32768
    const long long half = (long long)out_size / 2;  // re | im split

    ifft1024_r32ps_kernel<<<BLOCKS, THREADS>>>(re, im, out, half, rows);
}